// round 10
// baseline (speedup 1.0000x reference)
#include <cuda_runtime.h>
#include <cstdint>

// Two-kernel graph:
//  K1: fire-and-forget L2 prefetch of every gathered row (cp.async.bulk.prefetch.L2)
//      — no return tracking, so not bound by the ~2.1 TB/s miss-return cap.
//  K2: proven R1 gather (warp per row); misses merge with the in-flight
//      prefetch stream at LTS, late warps hit L2.

#define BATCH 16384
#define EMBED 128
#define ROW_BYTES 512

__global__ __launch_bounds__(512)
void prefetch_kernel(const int* __restrict__ i1,
                     const int* __restrict__ i2,
                     const float* __restrict__ W1,
                     const float* __restrict__ W2,
                     const float* __restrict__ b1,
                     const float* __restrict__ b2) {
    int t = blockIdx.x * blockDim.x + threadIdx.x;   // 0 .. 2*BATCH-1
    int second = t >= BATCH;
    int r = second ? t - BATCH : t;

    int idx = second ? __ldg(&i2[r]) : __ldg(&i1[r]);
    const float* row  = (second ? W2 : W1) + (size_t)idx * EMBED;
    const float* bias = (second ? b2 : b1) + idx;

    // 512B row -> L2, fire-and-forget (no MSHR/register return path).
    asm volatile("cp.async.bulk.prefetch.L2.global [%0], %1;"
                 :: "l"(row), "r"(ROW_BYTES) : "memory");
    // Bias line -> L2 (scalar prefetch, also fire-and-forget).
    asm volatile("prefetch.global.L2 [%0];" :: "l"(bias) : "memory");
}

__global__ __launch_bounds__(256)
void fused_embed_dot_kernel(const int* __restrict__ i1,
                            const int* __restrict__ i2,
                            const float* __restrict__ W1,
                            const float* __restrict__ W2,
                            const float* __restrict__ b1,
                            const float* __restrict__ b2,
                            float* __restrict__ out) {
    int warp_global = (blockIdx.x * blockDim.x + threadIdx.x) >> 5;
    int lane = threadIdx.x & 31;

    int idx1 = __ldg(&i1[warp_global]);
    int idx2 = __ldg(&i2[warp_global]);

    // Bias gathers early, overlapped with row gathers.
    float bv1 = __ldg(&b1[idx1]);
    float bv2 = __ldg(&b2[idx2]);

    const float4* r1 = reinterpret_cast<const float4*>(W1 + (size_t)idx1 * EMBED);
    const float4* r2 = reinterpret_cast<const float4*>(W2 + (size_t)idx2 * EMBED);

    float4 a = __ldg(&r1[lane]);
    float4 b = __ldg(&r2[lane]);

    float acc = a.x * b.x;
    acc = fmaf(a.y, b.y, acc);
    acc = fmaf(a.z, b.z, acc);
    acc = fmaf(a.w, b.w, acc);

    #pragma unroll
    for (int off = 16; off > 0; off >>= 1)
        acc += __shfl_xor_sync(0xFFFFFFFFu, acc, off);

    if (lane == 0)
        out[warp_global] = acc + bv1 + bv2;
}

extern "C" void kernel_launch(void* const* d_in, const int* in_sizes, int n_in,
                              void* d_out, int out_size) {
    const int*   i1 = (const int*)d_in[0];
    const int*   i2 = (const int*)d_in[1];
    const float* W1 = (const float*)d_in[2];
    const float* W2 = (const float*)d_in[3];
    const float* b1 = (const float*)d_in[4];
    const float* b2 = (const float*)d_in[5];
    float* out = (float*)d_out;

    // K1: 32768 prefetches, 64 blocks x 512 threads.
    prefetch_kernel<<<(2 * BATCH) / 512, 512>>>(i1, i2, W1, W2, b1, b2);
    // K2: gather + dot (R1 shape, best measured).
    fused_embed_dot_kernel<<<(BATCH * 32) / 256, 256>>>(i1, i2, W1, W2, b1, b2, out);
}

// round 11
// speedup vs baseline: 1.6618x; 1.6618x over previous
#include <cuda_runtime.h>

// out[r] = dot(W1[i1[r]], W2[i2[r]]) + b1[i1[r]] + b2[i2[r]]
// R1 shape x2: one warp handles TWO rows (w, w+8192). All 4 index loads,
// 4 row-gathers and 4 bias loads are in flight together (2x per-warp MLP on
// the dependent idx->row chain), and the two shuffle-reduction chains
// interleave to hide SHFL latency. 1024 blocks x 256 threads = 8192 warps.

#define BATCH 16384
#define EMBED 128  // 32 float4 per row
#define HALF  (BATCH / 2)

__global__ __launch_bounds__(256)
void fused_embed_dot_kernel(const int* __restrict__ i1,
                            const int* __restrict__ i2,
                            const float* __restrict__ W1,
                            const float* __restrict__ W2,
                            const float* __restrict__ b1,
                            const float* __restrict__ b2,
                            float* __restrict__ out) {
    int w    = (blockIdx.x * blockDim.x + threadIdx.x) >> 5;  // 0..8191
    int lane = threadIdx.x & 31;

    int rowA = w;
    int rowB = w + HALF;

    // Four independent index loads (contiguous across warps -> coalesced).
    int idxA1 = __ldg(&i1[rowA]);
    int idxA2 = __ldg(&i2[rowA]);
    int idxB1 = __ldg(&i1[rowB]);
    int idxB2 = __ldg(&i2[rowB]);

    // Bias gathers hoisted — overlap with the row gathers.
    float bvA = __ldg(&b1[idxA1]) + __ldg(&b2[idxA2]);
    float bvB = __ldg(&b1[idxB1]) + __ldg(&b2[idxB2]);

    const float4* rA1 = reinterpret_cast<const float4*>(W1 + (size_t)idxA1 * EMBED);
    const float4* rA2 = reinterpret_cast<const float4*>(W2 + (size_t)idxA2 * EMBED);
    const float4* rB1 = reinterpret_cast<const float4*>(W1 + (size_t)idxB1 * EMBED);
    const float4* rB2 = reinterpret_cast<const float4*>(W2 + (size_t)idxB2 * EMBED);

    // Four independent LDG.128 per lane.
    float4 aA = __ldg(&rA1[lane]);
    float4 cA = __ldg(&rA2[lane]);
    float4 aB = __ldg(&rB1[lane]);
    float4 cB = __ldg(&rB2[lane]);

    float accA = aA.x * cA.x;
    float accB = aB.x * cB.x;
    accA = fmaf(aA.y, cA.y, accA);  accB = fmaf(aB.y, cB.y, accB);
    accA = fmaf(aA.z, cA.z, accA);  accB = fmaf(aB.z, cB.z, accB);
    accA = fmaf(aA.w, cA.w, accA);  accB = fmaf(aB.w, cB.w, accB);

    // Two interleaved butterfly reductions (independent chains hide SHFL lat).
    #pragma unroll
    for (int off = 16; off > 0; off >>= 1) {
        accA += __shfl_xor_sync(0xFFFFFFFFu, accA, off);
        accB += __shfl_xor_sync(0xFFFFFFFFu, accB, off);
    }

    if (lane == 0) {
        out[rowA] = accA + bvA;
        out[rowB] = accB + bvB;
    }
}

extern "C" void kernel_launch(void* const* d_in, const int* in_sizes, int n_in,
                              void* d_out, int out_size) {
    const int*   i1 = (const int*)d_in[0];
    const int*   i2 = (const int*)d_in[1];
    const float* W1 = (const float*)d_in[2];
    const float* W2 = (const float*)d_in[3];
    const float* b1 = (const float*)d_in[4];
    const float* b2 = (const float*)d_in[5];
    float* out = (float*)d_out;

    // 8192 warps (2 rows each) / 8 warps per block = 1024 blocks.
    fused_embed_dot_kernel<<<(HALF * 32) / 256, 256>>>(i1, i2, W1, W2, b1, b2, out);
}